// round 12
// baseline (speedup 1.0000x reference)
#include <cuda_runtime.h>
#include <cstdint>

// Problem shape (fixed by reference setup_inputs)
#define B_ 8
#define C_ 128
#define H_ 256
#define W_ 256
#define N_ (H_ * W_)     // 65536 pixels per image
#define S_ 1024          // segments per image
#define PLANE4 (N_ / 4)  // plane stride in float4 units = 16384

#define F4_TOTAL (B_ * S_ * C_ / 4)   // 262144 float4 in accumulator/output

// Accumulator scratch. Zero at static init; finalize re-zeroes g_accum and
// zero_counts_kernel re-zeroes g_counts every call, so the "zero at entry"
// invariant holds across graph replays.
__device__ float g_accum[B_ * S_ * C_];
__device__ float g_counts[B_ * S_];

// ---------------------------------------------------------------------------
// Scatter + fused count.  grid: (16 chunks, C_/4 channel-groups, B_),
// block 256.  __launch_bounds__(256, 6) caps regs at 40 -> 6 CTAs/SM
// (75% theoretical occupancy vs 62.5% at the unconstrained 44 regs).
// Addresses kept as 32-bit element offsets (seg*C_) until the REDG to
// reduce live register state.
// Per thread, per group of 4 consecutive pixels:
//   1x LDG.128 labels + 4x LDG.128 planes + 4x red.global.add.v4.f32
// ---------------------------------------------------------------------------
__global__ void __launch_bounds__(256, 6) scatter_kernel(
    const float* __restrict__ in,
    const int* __restrict__ labels)
{
    __shared__ int hist[S_];

    const int b     = blockIdx.z;
    const int cg    = blockIdx.y;    // channel group of 4
    const int chunk = blockIdx.x;    // 4096-pixel spatial chunk
    const int t     = threadIdx.x;
    const bool do_count = (cg == 0);   // uniform per block

    if (do_count) {
        for (int i = t; i < S_; i += 256) hist[i] = 0;
        __syncthreads();
    }

    const float4* p0 = reinterpret_cast<const float4*>(
                           in + ((size_t)b * C_ + (size_t)cg * 4) * N_)
                       + chunk * 1024;
    const int4* lab4 = reinterpret_cast<const int4*>(
                           labels + (size_t)b * N_ + chunk * 4096);
    // base of this (b, cg) column in the accumulator
    float* const ob = g_accum + (size_t)b * S_ * C_ + cg * 4;

    #pragma unroll
    for (int g = 0; g < 4; g++) {
        const int idx = g * 256 + t;               // float4 index within chunk
        const int4 sg = lab4[idx];
        const float4 x0 = p0[idx];                 // channel cg*4+0, pixels p..p+3
        const float4 x1 = p0[PLANE4     + idx];    // channel cg*4+1
        const float4 x2 = p0[2 * PLANE4 + idx];    // channel cg*4+2
        const float4 x3 = p0[3 * PLANE4 + idx];    // channel cg*4+3

        if (do_count) {
            atomicAdd(&hist[sg.x], 1);
            atomicAdd(&hist[sg.y], 1);
            atomicAdd(&hist[sg.z], 1);
            atomicAdd(&hist[sg.w], 1);
        }

        // 32-bit offsets; address formed at the REDG (folds into LEA)
        const int r0 = sg.x * C_;
        const int r1 = sg.y * C_;
        const int r2 = sg.z * C_;
        const int r3 = sg.w * C_;
        asm volatile("red.global.add.v4.f32 [%0], {%1, %2, %3, %4};"
                     :: "l"(ob + r0), "f"(x0.x), "f"(x1.x), "f"(x2.x), "f"(x3.x) : "memory");
        asm volatile("red.global.add.v4.f32 [%0], {%1, %2, %3, %4};"
                     :: "l"(ob + r1), "f"(x0.y), "f"(x1.y), "f"(x2.y), "f"(x3.y) : "memory");
        asm volatile("red.global.add.v4.f32 [%0], {%1, %2, %3, %4};"
                     :: "l"(ob + r2), "f"(x0.z), "f"(x1.z), "f"(x2.z), "f"(x3.z) : "memory");
        asm volatile("red.global.add.v4.f32 [%0], {%1, %2, %3, %4};"
                     :: "l"(ob + r3), "f"(x0.w), "f"(x1.w), "f"(x2.w), "f"(x3.w) : "memory");
    }

    if (do_count) {
        __syncthreads();
        for (int i = t; i < S_; i += 256) {
            int v = hist[i];
            if (v) atomicAdd(&g_counts[b * S_ + i], (float)v);
        }
    }
}

// ---------------------------------------------------------------------------
// Finalize: out = acc / max(cnt,1); re-zero acc. MLP-oriented, no barriers.
// grid 256 x block 256.
// ---------------------------------------------------------------------------
__global__ void __launch_bounds__(256) finalize_kernel(float4* __restrict__ out) {
    const int gt = blockIdx.x * blockDim.x + threadIdx.x;   // 0..65535
    float4* acc = reinterpret_cast<float4*>(g_accum);

    float  cnt[4];
    float4 v[4];
    #pragma unroll
    for (int j = 0; j < 4; j++) {
        const int idx = gt + j * (F4_TOTAL / 4);
        cnt[j] = g_counts[idx >> 5];     // idx / (C_/4): one (b,s) per 32 f4
        v[j]   = acc[idx];
    }
    #pragma unroll
    for (int j = 0; j < 4; j++) {
        const int idx = gt + j * (F4_TOTAL / 4);
        const float s = 1.0f / fmaxf(cnt[j], 1.0f);
        v[j].x *= s; v[j].y *= s; v[j].z *= s; v[j].w *= s;
        out[idx] = v[j];
        acc[idx] = make_float4(0.f, 0.f, 0.f, 0.f);   // restore zero invariant
    }
}

// ---------------------------------------------------------------------------
// Zero counts for the next graph replay. 32KB, float4 stores.
// ---------------------------------------------------------------------------
__global__ void zero_counts_kernel() {
    float4* c = reinterpret_cast<float4*>(g_counts);
    c[blockIdx.x * blockDim.x + threadIdx.x] = make_float4(0.f, 0.f, 0.f, 0.f);
}

// ---------------------------------------------------------------------------
// kernel_launch: scatter -> finalize -> zero_counts  (3 launches; scatter at
// position 0 so ncu's effective index-15 capture lands on it: 15 % 3 == 0)
// ---------------------------------------------------------------------------
extern "C" void kernel_launch(void* const* d_in, const int* in_sizes, int n_in,
                              void* d_out, int out_size) {
    const float* in     = (const float*)d_in[0];
    const int*   labels = (const int*)d_in[1];

    scatter_kernel<<<dim3(16, C_ / 4, B_), 256>>>(in, labels);

    finalize_kernel<<<256, 256>>>((float4*)d_out);

    zero_counts_kernel<<<2, 1024>>>();
}

// round 13
// speedup vs baseline: 1.0467x; 1.0467x over previous
#include <cuda_runtime.h>
#include <cstdint>

// Problem shape (fixed by reference setup_inputs)
#define B_ 8
#define C_ 128
#define H_ 256
#define W_ 256
#define N_ (H_ * W_)     // 65536 pixels per image
#define S_ 1024          // segments per image
#define PLANE4 (N_ / 4)  // plane stride in float4 units = 16384

#define F4_TOTAL (B_ * S_ * C_ / 4)   // 262144 float4 in accumulator/output

// Accumulator scratch. Zero at static init; finalize re-zeroes both g_accum
// and g_counts after reading, so the "zero at entry" invariant holds across
// graph replays.
__device__ float g_accum[B_ * S_ * C_];
__device__ float g_counts[B_ * S_];

// ---------------------------------------------------------------------------
// Scatter + fused count — EXACT round-9 best configuration (105.8us).
// grid: (16 pixel-chunks, C_/4 channel-groups, B_), block 256, regs=44.
// Per thread, per group of 4 consecutive pixels:
//   1x LDG.128 labels + 4x LDG.128 planes + 4x red.global.add.v4.f32
// cg==0 blocks additionally histogram their chunk's labels into g_counts.
// (Do NOT add launch_bounds occupancy caps: 65% occ measured SLOWER than
// 54% — LTS atomic path is conflict-saturated, extra warps only collide.)
// ---------------------------------------------------------------------------
__global__ void __launch_bounds__(256) scatter_kernel(
    const float* __restrict__ in,
    const int* __restrict__ labels)
{
    __shared__ int hist[S_];

    const int b     = blockIdx.z;
    const int cg    = blockIdx.y;    // channel group of 4
    const int chunk = blockIdx.x;    // 4096-pixel spatial chunk
    const int t     = threadIdx.x;
    const bool do_count = (cg == 0);   // uniform per block

    if (do_count) {
        for (int i = t; i < S_; i += 256) hist[i] = 0;
        __syncthreads();
    }

    const float4* p0 = reinterpret_cast<const float4*>(
                           in + ((size_t)b * C_ + (size_t)cg * 4) * N_)
                       + chunk * 1024;
    const int4* lab4 = reinterpret_cast<const int4*>(
                           labels + (size_t)b * N_ + chunk * 4096);
    float* ob = g_accum + (size_t)b * S_ * C_ + cg * 4;

    #pragma unroll
    for (int g = 0; g < 4; g++) {
        const int idx = g * 256 + t;               // float4 index within chunk
        const float4 x0 = p0[idx];                 // channel cg*4+0, pixels p..p+3
        const float4 x1 = p0[PLANE4     + idx];    // channel cg*4+1
        const float4 x2 = p0[2 * PLANE4 + idx];    // channel cg*4+2
        const float4 x3 = p0[3 * PLANE4 + idx];    // channel cg*4+3
        const int4 sg = lab4[idx];

        if (do_count) {
            atomicAdd(&hist[sg.x], 1);
            atomicAdd(&hist[sg.y], 1);
            atomicAdd(&hist[sg.z], 1);
            atomicAdd(&hist[sg.w], 1);
        }

        float* a0 = ob + (size_t)sg.x * C_;
        float* a1 = ob + (size_t)sg.y * C_;
        float* a2 = ob + (size_t)sg.z * C_;
        float* a3 = ob + (size_t)sg.w * C_;
        asm volatile("red.global.add.v4.f32 [%0], {%1, %2, %3, %4};"
                     :: "l"(a0), "f"(x0.x), "f"(x1.x), "f"(x2.x), "f"(x3.x) : "memory");
        asm volatile("red.global.add.v4.f32 [%0], {%1, %2, %3, %4};"
                     :: "l"(a1), "f"(x0.y), "f"(x1.y), "f"(x2.y), "f"(x3.y) : "memory");
        asm volatile("red.global.add.v4.f32 [%0], {%1, %2, %3, %4};"
                     :: "l"(a2), "f"(x0.z), "f"(x1.z), "f"(x2.z), "f"(x3.z) : "memory");
        asm volatile("red.global.add.v4.f32 [%0], {%1, %2, %3, %4};"
                     :: "l"(a3), "f"(x0.w), "f"(x1.w), "f"(x2.w), "f"(x3.w) : "memory");
    }

    if (do_count) {
        __syncthreads();
        for (int i = t; i < S_; i += 256) {
            int v = hist[i];
            if (v) atomicAdd(&g_counts[b * S_ + i], (float)v);
        }
    }
}

// ---------------------------------------------------------------------------
// Finalize + counts re-zero (fused): out = acc / max(cnt,1); zero acc & cnt.
// grid 256 x block 256; each thread handles 4 float4s at 64K stride (8
// independent loads in flight, no block barriers).
// Counts zeroing is safe warp-locally: the 32 readers of count word
// (w + j*2048) are exactly the lanes of warp w at iteration j (broadcast
// load), so after __syncwarp() lane 0 may zero it.
// ---------------------------------------------------------------------------
__global__ void __launch_bounds__(256) finalize_kernel(float4* __restrict__ out) {
    const int gt = blockIdx.x * blockDim.x + threadIdx.x;   // 0..65535
    float4* acc = reinterpret_cast<float4*>(g_accum);

    float  cnt[4];
    float4 v[4];
    #pragma unroll
    for (int j = 0; j < 4; j++) {
        const int idx = gt + j * (F4_TOTAL / 4);
        cnt[j] = g_counts[idx >> 5];     // idx / (C_/4): one (b,s) per 32 f4
        v[j]   = acc[idx];
    }

    __syncwarp();                        // all lanes' count reads complete
    if ((threadIdx.x & 31) == 0) {
        #pragma unroll
        for (int j = 0; j < 4; j++) {
            const int idx = gt + j * (F4_TOTAL / 4);
            g_counts[idx >> 5] = 0.0f;   // restore zero invariant
        }
    }

    #pragma unroll
    for (int j = 0; j < 4; j++) {
        const int idx = gt + j * (F4_TOTAL / 4);
        const float s = 1.0f / fmaxf(cnt[j], 1.0f);
        v[j].x *= s; v[j].y *= s; v[j].z *= s; v[j].w *= s;
        out[idx] = v[j];
        acc[idx] = make_float4(0.f, 0.f, 0.f, 0.f);   // restore zero invariant
    }
}

// ---------------------------------------------------------------------------
// kernel_launch: scatter -> finalize.  2 launches, graph-capturable.
// ---------------------------------------------------------------------------
extern "C" void kernel_launch(void* const* d_in, const int* in_sizes, int n_in,
                              void* d_out, int out_size) {
    const float* in     = (const float*)d_in[0];
    const int*   labels = (const int*)d_in[1];

    scatter_kernel<<<dim3(16, C_ / 4, B_), 256>>>(in, labels);

    finalize_kernel<<<256, 256>>>((float4*)d_out);
}

// round 14
// speedup vs baseline: 1.0657x; 1.0181x over previous
#include <cuda_runtime.h>
#include <cstdint>

// Problem shape (fixed by reference setup_inputs)
#define B_ 8
#define C_ 128
#define H_ 256
#define W_ 256
#define N_ (H_ * W_)     // 65536 pixels per image
#define S_ 1024          // segments per image
#define PLANE4 (N_ / 4)  // plane stride in float4 units = 16384

#define ACC_ELEMS (B_ * S_ * C_)      // 1M floats per replica
#define F4_TOTAL (ACC_ELEMS / 4)      // 262144 float4 per replica

// TWO accumulator replicas: scatter CTAs alternate by chunk parity, halving
// per-word LTS atomic conflict degree. Zero at static init; finalize
// re-zeroes both (and g_counts), preserving the zero-at-entry invariant
// across graph replays.
__device__ float g_accum0[ACC_ELEMS];
__device__ float g_accum1[ACC_ELEMS];
__device__ float g_counts[B_ * S_];

// ---------------------------------------------------------------------------
// Scatter + fused count — round-9 best structure, plus replica selection.
// grid: (16 pixel-chunks, C_/4 channel-groups, B_), block 256.
// Per thread, per group of 4 consecutive pixels:
//   1x LDG.128 labels + 4x LDG.128 planes + 4x red.global.add.v4.f32
// Replica = chunk & 1: odd/even chunk CTAs hit disjoint accumulators, so
// concurrent REDGs to the same (b,seg,word) are split across two addresses.
// cg==0 blocks additionally histogram their chunk's labels into g_counts.
// ---------------------------------------------------------------------------
__global__ void __launch_bounds__(256) scatter_kernel(
    const float* __restrict__ in,
    const int* __restrict__ labels)
{
    __shared__ int hist[S_];

    const int b     = blockIdx.z;
    const int cg    = blockIdx.y;    // channel group of 4
    const int chunk = blockIdx.x;    // 4096-pixel spatial chunk
    const int t     = threadIdx.x;
    const bool do_count = (cg == 0);   // uniform per block

    if (do_count) {
        for (int i = t; i < S_; i += 256) hist[i] = 0;
        __syncthreads();
    }

    const float4* p0 = reinterpret_cast<const float4*>(
                           in + ((size_t)b * C_ + (size_t)cg * 4) * N_)
                       + chunk * 1024;
    const int4* lab4 = reinterpret_cast<const int4*>(
                           labels + (size_t)b * N_ + chunk * 4096);
    float* const rep = (chunk & 1) ? g_accum1 : g_accum0;
    float* ob = rep + (size_t)b * S_ * C_ + cg * 4;

    #pragma unroll
    for (int g = 0; g < 4; g++) {
        const int idx = g * 256 + t;               // float4 index within chunk
        const float4 x0 = p0[idx];                 // channel cg*4+0, pixels p..p+3
        const float4 x1 = p0[PLANE4     + idx];    // channel cg*4+1
        const float4 x2 = p0[2 * PLANE4 + idx];    // channel cg*4+2
        const float4 x3 = p0[3 * PLANE4 + idx];    // channel cg*4+3
        const int4 sg = lab4[idx];

        if (do_count) {
            atomicAdd(&hist[sg.x], 1);
            atomicAdd(&hist[sg.y], 1);
            atomicAdd(&hist[sg.z], 1);
            atomicAdd(&hist[sg.w], 1);
        }

        float* a0 = ob + (size_t)sg.x * C_;
        float* a1 = ob + (size_t)sg.y * C_;
        float* a2 = ob + (size_t)sg.z * C_;
        float* a3 = ob + (size_t)sg.w * C_;
        asm volatile("red.global.add.v4.f32 [%0], {%1, %2, %3, %4};"
                     :: "l"(a0), "f"(x0.x), "f"(x1.x), "f"(x2.x), "f"(x3.x) : "memory");
        asm volatile("red.global.add.v4.f32 [%0], {%1, %2, %3, %4};"
                     :: "l"(a1), "f"(x0.y), "f"(x1.y), "f"(x2.y), "f"(x3.y) : "memory");
        asm volatile("red.global.add.v4.f32 [%0], {%1, %2, %3, %4};"
                     :: "l"(a2), "f"(x0.z), "f"(x1.z), "f"(x2.z), "f"(x3.z) : "memory");
        asm volatile("red.global.add.v4.f32 [%0], {%1, %2, %3, %4};"
                     :: "l"(a3), "f"(x0.w), "f"(x1.w), "f"(x2.w), "f"(x3.w) : "memory");
    }

    if (do_count) {
        __syncthreads();
        for (int i = t; i < S_; i += 256) {
            int v = hist[i];
            if (v) atomicAdd(&g_counts[b * S_ + i], (float)v);
        }
    }
}

// ---------------------------------------------------------------------------
// Finalize: out = (acc0+acc1) / max(cnt,1); zero acc0, acc1, counts.
// grid 1024 x block 256 (one float4 per thread -> full occupancy, vs 14.6%
// at grid 256). Warp w's 32 lanes are exactly the 32 readers of count word
// gt>>5, so after __syncwarp() lane 0 may zero it — no block barriers.
// ---------------------------------------------------------------------------
__global__ void __launch_bounds__(256) finalize_kernel(float4* __restrict__ out) {
    const int gt = blockIdx.x * blockDim.x + threadIdx.x;   // 0..F4_TOTAL-1
    float4* acc0 = reinterpret_cast<float4*>(g_accum0);
    float4* acc1 = reinterpret_cast<float4*>(g_accum1);

    const float cnt = g_counts[gt >> 5];
    const float4 u = acc0[gt];
    const float4 w = acc1[gt];

    __syncwarp();
    if ((threadIdx.x & 31) == 0) g_counts[gt >> 5] = 0.0f;

    const float s = 1.0f / fmaxf(cnt, 1.0f);
    float4 v;
    v.x = (u.x + w.x) * s;
    v.y = (u.y + w.y) * s;
    v.z = (u.z + w.z) * s;
    v.w = (u.w + w.w) * s;
    out[gt] = v;
    const float4 z = make_float4(0.f, 0.f, 0.f, 0.f);
    acc0[gt] = z;                       // restore zero invariant
    acc1[gt] = z;
}

// ---------------------------------------------------------------------------
// kernel_launch: scatter -> finalize.  2 launches, graph-capturable.
// ---------------------------------------------------------------------------
extern "C" void kernel_launch(void* const* d_in, const int* in_sizes, int n_in,
                              void* d_out, int out_size) {
    const float* in     = (const float*)d_in[0];
    const int*   labels = (const int*)d_in[1];

    scatter_kernel<<<dim3(16, C_ / 4, B_), 256>>>(in, labels);

    finalize_kernel<<<F4_TOTAL / 256, 256>>>((float4*)d_out);
}